// round 12
// baseline (speedup 1.0000x reference)
#include <cuda_runtime.h>

// VanillaRNN fused persistent kernel, v10 = v9 + explicit 1-block-lookahead
// software pipeline so the smem crossbar (1536 cyc/step) and the FMA pipe
// (~1776 cyc/step) stream concurrently instead of alternating in bursts.
// B=1024, T=512, I=64, H=128, O=10.
// Grid: 128 CTAs x 8 rows (two independent 4-row groups), 256 threads,
// 1 CTA/SM (__launch_bounds__(256,1)); both groups share the 96 weight regs.
//
// Thread mapping per group (select-free): g = warp*4 + (lane&3): column
// group, cols {g+32*cg[c]}; seg = lane>>2 in [0,8): 24-wide k-segment of the
// 192-wide concat(x_t, h_t). Butterfly xor4/xor8/xor16 as pure
// keep + shfl_xor(send) via per-thread row/col permutation.
// Step body: 8 row-blocks; each block = 6 LDS.128 into named Blk registers +
// 48 FFMA2. Loads of block i+1/i+2 are issued before block i's FMAs; each
// pair's stage-0 shuffle is folded immediately after its two accs complete.
// tanh via MUFU tanh.approx.f32. One __syncthreads per timestep.
// Segment stride 28 floats: 8 bases tile all 32 banks -> conflict-free LDS.128.

#define ROWS 4          // rows per group
#define NGROUPS 2
#define NTHREADS 256
#define HDIM 128
#define IDIM 64
#define TSTEPS 512
#define ODIM 10
#define SEGF 24
#define SEGP 28
#define RSTRIDE 228
#define GRID 128

__device__ __forceinline__ unsigned long long ffma2(unsigned long long a,
                                                    unsigned long long b,
                                                    unsigned long long c) {
    unsigned long long d;
    asm("fma.rn.f32x2 %0, %1, %2, %3;" : "=l"(d) : "l"(a), "l"(b), "l"(c));
    return d;
}

__device__ __forceinline__ unsigned long long packf2(float lo, float hi) {
    return ((unsigned long long)__float_as_uint(hi) << 32) |
           (unsigned long long)__float_as_uint(lo);
}

__device__ __forceinline__ float sum2(unsigned long long a) {
    return __uint_as_float((unsigned)a) + __uint_as_float((unsigned)(a >> 32));
}

__device__ __forceinline__ float tanh_fast(float z) {
    float r;
    asm("tanh.approx.f32 %0, %1;" : "=f"(r) : "f"(z));
    return r;
}

__device__ __forceinline__ int physk(int k) { return k + 4 * (k / SEGF); }

__device__ __forceinline__ float wpick(const float* __restrict__ W_hx,
                                       const float* __restrict__ W_hh,
                                       int o, int k) {
    return (k < IDIM) ? W_hx[o * IDIM + k] : W_hh[o * HDIM + (k - IDIM)];
}

// one row-block's data: 24 floats = 6 x 16B
struct Blk {
    ulonglong2 v0, v1, v2, v3, v4, v5;
};

__device__ __forceinline__ Blk ldblk(const float* __restrict__ p) {
    const ulonglong2* q = (const ulonglong2*)p;
    Blk b;
    b.v0 = q[0]; b.v1 = q[1]; b.v2 = q[2];
    b.v3 = q[3]; b.v4 = q[4]; b.v5 = q[5];
    return b;
}

// 48 FFMA2 over one block for this thread's 4 (permuted) cols
__device__ __forceinline__ void accblk(const Blk& b,
                                       const unsigned long long w[4][12],
                                       float sv[4]) {
    unsigned long long a0 = 0ull, a1 = 0ull, a2 = 0ull, a3 = 0ull;
    a0 = ffma2(b.v0.x, w[0][0], a0);  a1 = ffma2(b.v0.x, w[1][0], a1);
    a2 = ffma2(b.v0.x, w[2][0], a2);  a3 = ffma2(b.v0.x, w[3][0], a3);
    a0 = ffma2(b.v0.y, w[0][1], a0);  a1 = ffma2(b.v0.y, w[1][1], a1);
    a2 = ffma2(b.v0.y, w[2][1], a2);  a3 = ffma2(b.v0.y, w[3][1], a3);
    a0 = ffma2(b.v1.x, w[0][2], a0);  a1 = ffma2(b.v1.x, w[1][2], a1);
    a2 = ffma2(b.v1.x, w[2][2], a2);  a3 = ffma2(b.v1.x, w[3][2], a3);
    a0 = ffma2(b.v1.y, w[0][3], a0);  a1 = ffma2(b.v1.y, w[1][3], a1);
    a2 = ffma2(b.v1.y, w[2][3], a2);  a3 = ffma2(b.v1.y, w[3][3], a3);
    a0 = ffma2(b.v2.x, w[0][4], a0);  a1 = ffma2(b.v2.x, w[1][4], a1);
    a2 = ffma2(b.v2.x, w[2][4], a2);  a3 = ffma2(b.v2.x, w[3][4], a3);
    a0 = ffma2(b.v2.y, w[0][5], a0);  a1 = ffma2(b.v2.y, w[1][5], a1);
    a2 = ffma2(b.v2.y, w[2][5], a2);  a3 = ffma2(b.v2.y, w[3][5], a3);
    a0 = ffma2(b.v3.x, w[0][6], a0);  a1 = ffma2(b.v3.x, w[1][6], a1);
    a2 = ffma2(b.v3.x, w[2][6], a2);  a3 = ffma2(b.v3.x, w[3][6], a3);
    a0 = ffma2(b.v3.y, w[0][7], a0);  a1 = ffma2(b.v3.y, w[1][7], a1);
    a2 = ffma2(b.v3.y, w[2][7], a2);  a3 = ffma2(b.v3.y, w[3][7], a3);
    a0 = ffma2(b.v4.x, w[0][8], a0);  a1 = ffma2(b.v4.x, w[1][8], a1);
    a2 = ffma2(b.v4.x, w[2][8], a2);  a3 = ffma2(b.v4.x, w[3][8], a3);
    a0 = ffma2(b.v4.y, w[0][9], a0);  a1 = ffma2(b.v4.y, w[1][9], a1);
    a2 = ffma2(b.v4.y, w[2][9], a2);  a3 = ffma2(b.v4.y, w[3][9], a3);
    a0 = ffma2(b.v5.x, w[0][10], a0); a1 = ffma2(b.v5.x, w[1][10], a1);
    a2 = ffma2(b.v5.x, w[2][10], a2); a3 = ffma2(b.v5.x, w[3][10], a3);
    a0 = ffma2(b.v5.y, w[0][11], a0); a1 = ffma2(b.v5.y, w[1][11], a1);
    a2 = ffma2(b.v5.y, w[2][11], a2); a3 = ffma2(b.v5.y, w[3][11], a3);
    sv[0] = sum2(a0); sv[1] = sum2(a1); sv[2] = sum2(a2); sv[3] = sum2(a3);
}

__global__ void __launch_bounds__(NTHREADS, 1)
rnn_fused_kernel(const float* __restrict__ x,
                 const float* __restrict__ W_hx,
                 const float* __restrict__ W_hh,
                 const float* __restrict__ b_hh,
                 const float* __restrict__ W_ph,
                 const float* __restrict__ b_ph,
                 float* __restrict__ out) {
    // buf[group][pingpong][row][phys-k]
    __shared__ __align__(16) float buf[NGROUPS][2][ROWS][RSTRIDE];

    const int tid  = threadIdx.x;
    const int lane = tid & 31;
    const int warp = tid >> 5;
    const int g    = warp * 4 + (lane & 3);   // col group 0..31
    const int seg  = lane >> 2;               // k-segment 0..7
    const int kb   = seg * SEGF;
    const int b0r  = blockIdx.x * (ROWS * NGROUPS);

    const int sb0 = seg & 1, sb1 = (seg >> 1) & 1, sb2 = (seg >> 2) & 1;

    // per-thread permuted column order (stage-2 select elimination)
    int cg[4];
    cg[0] = 2 * sb2; cg[1] = 2 * sb2 + 1;
    cg[2] = 2 * (1 - sb2); cg[3] = 2 * (1 - sb2) + 1;

    // ---- weights in permuted col order: 48 ULL = 96 regs, SHARED by groups
    unsigned long long w[4][12];
#pragma unroll
    for (int c = 0; c < 4; c++) {
        const int o = g + 32 * cg[c];
#pragma unroll
        for (int j = 0; j < 12; j++) {
            const int k0 = kb + 2 * j;
            w[c][j] = packf2(wpick(W_hx, W_hh, o, k0),
                             wpick(W_hx, W_hh, o, k0 + 1));
        }
    }

    // per-thread row order (stage-0/1 select elimination)
    const int rKA = sb1 + 2 * sb0;
    const int rSA = sb1 + 2 * (1 - sb0);
    const int rKB = (1 - sb1) + 2 * sb0;
    const int rSB = (1 - sb1) + 2 * (1 - sb0);
    const int segoff = seg * SEGP;
    const int oKA = rKA * RSTRIDE + segoff;
    const int oSA = rSA * RSTRIDE + segoff;
    const int oKB = rKB * RSTRIDE + segoff;
    const int oSB = rSB * RSTRIDE + segoff;

    const int mstar = 2 * sb0 + sb1;          // row this lane finalizes
    const int of0 = g + 32 * cg[0];
    const int of1 = g + 32 * cg[1];
    const float bb0 = b_hh[of0];
    const float bb1 = b_hh[of1];
    const int ph0 = physk(IDIM + of0);
    const int ph1 = physk(IDIM + of1);

    // ---- zero all buffers (h0 = 0)
    for (int i = tid; i < NGROUPS * 2 * ROWS * RSTRIDE; i += NTHREADS)
        ((float*)buf)[i] = 0.0f;

    // ---- x loader: tid<128 -> global row xr = tid>>4 (0..7), chunk c4
    const int xr   = tid >> 4;
    const int xgrp = (xr >> 2) & 1;
    const int xrl  = xr & 3;
    const int c4   = (tid & 15) * 4;
    const int pc4  = c4 + 4 * (c4 / SEGF);
    const bool loader = (tid < 128);
    const float* xrow = x + (size_t)(b0r + (xr & 7)) * TSTEPS * IDIM;

    if (loader)
        *(float4*)&buf[xgrp][0][xrl][pc4] = *(const float4*)(xrow + c4);
    __syncthreads();

    int p = 0;
    for (int t = 0; t < TSTEPS; t++) {
        float4 xn;
        if (loader) {
            const int tn = (t + 1 < TSTEPS) ? t + 1 : TSTEPS - 1;
            xn = *(const float4*)(xrow + (size_t)tn * IDIM + c4);
        }

        const float* base0 = &buf[0][p][0][0];
        const float* base1 = &buf[1][p][0][0];

        // ---- pipelined 8-block schedule: loads run 1-2 blocks ahead of FMAs;
        // stage-0 shuffles fold in as soon as each pair completes.
        Blk b0 = ldblk(base0 + oKA);
        Blk b1 = ldblk(base0 + oSA);
        Blk b2 = ldblk(base1 + oKA);

        float aKA0[4]; accblk(b0, w, aKA0);
        Blk b3 = ldblk(base1 + oSA);
        float aSA0[4]; accblk(b1, w, aSA0);
        Blk b4 = ldblk(base0 + oKB);

        float ra0[4];
#pragma unroll
        for (int c = 0; c < 4; c++)
            ra0[c] = aKA0[c] + __shfl_xor_sync(0xffffffffu, aSA0[c], 4);

        float aKA1[4]; accblk(b2, w, aKA1);
        Blk b5 = ldblk(base0 + oSB);
        float aSA1[4]; accblk(b3, w, aSA1);
        Blk b6 = ldblk(base1 + oKB);

        float ra1[4];
#pragma unroll
        for (int c = 0; c < 4; c++)
            ra1[c] = aKA1[c] + __shfl_xor_sync(0xffffffffu, aSA1[c], 4);

        float aKB0[4]; accblk(b4, w, aKB0);
        Blk b7 = ldblk(base1 + oSB);
        float aSB0[4]; accblk(b5, w, aSB0);

        float rb0[4];
#pragma unroll
        for (int c = 0; c < 4; c++)
            rb0[c] = aKB0[c] + __shfl_xor_sync(0xffffffffu, aSB0[c], 4);

        float aKB1[4]; accblk(b6, w, aKB1);
        float aSB1[4]; accblk(b7, w, aSB1);

        float rb1[4];
#pragma unroll
        for (int c = 0; c < 4; c++)
            rb1[c] = aKB1[c] + __shfl_xor_sync(0xffffffffu, aSB1[c], 4);

        // ---- stage 1 (xor 8)
        float rc0[4], rc1[4];
#pragma unroll
        for (int c = 0; c < 4; c++) {
            rc0[c] = ra0[c] + __shfl_xor_sync(0xffffffffu, rb0[c], 8);
            rc1[c] = ra1[c] + __shfl_xor_sync(0xffffffffu, rb1[c], 8);
        }

        // ---- stage 2 (xor 16)
        const float f00 = rc0[0] + __shfl_xor_sync(0xffffffffu, rc0[2], 16);
        const float f10 = rc1[0] + __shfl_xor_sync(0xffffffffu, rc1[2], 16);
        const float f01 = rc0[1] + __shfl_xor_sync(0xffffffffu, rc0[3], 16);
        const float f11 = rc1[1] + __shfl_xor_sync(0xffffffffu, rc1[3], 16);

        // ---- publish h_t for both groups
        const int q = p ^ 1;
        buf[0][q][mstar][ph0] = tanh_fast(f00 + bb0);
        buf[0][q][mstar][ph1] = tanh_fast(f01 + bb1);
        buf[1][q][mstar][ph0] = tanh_fast(f10 + bb0);
        buf[1][q][mstar][ph1] = tanh_fast(f11 + bb1);

        if (loader) *(float4*)&buf[xgrp][q][xrl][pc4] = xn;

        __syncthreads();
        p = q;
    }

    // ---- final projection over all 8 rows
    if (tid < ROWS * NGROUPS * ODIM) {
        const int m = tid / ODIM;             // 0..7
        const int j = tid % ODIM;
        const int mg = m >> 2, mr = m & 3;
        float s = b_ph[j];
#pragma unroll 4
        for (int k = 0; k < HDIM; k++)
            s += buf[mg][p][mr][physk(IDIM + k)] * W_ph[j * HDIM + k];
        out[(size_t)(b0r + m) * ODIM + j] = s;
    }
}

extern "C" void kernel_launch(void* const* d_in, const int* in_sizes, int n_in,
                              void* d_out, int out_size) {
    const float* x    = (const float*)d_in[0];
    const float* W_hx = (const float*)d_in[1];
    const float* W_hh = (const float*)d_in[2];
    const float* b_hh = (const float*)d_in[3];
    const float* W_ph = (const float*)d_in[4];
    const float* b_ph = (const float*)d_in[5];
    float* out = (float*)d_out;

    rnn_fused_kernel<<<GRID, NTHREADS>>>(x, W_hx, W_hh, b_hh, W_ph, b_ph, out);
}